// round 16
// baseline (speedup 1.0000x reference)
#include <cuda_runtime.h>
#include <cuda_fp16.h>
#include <cstdint>

#define TPB    256           // 8 warps = 4 M-groups (32 rows) x 2 N-groups
#define ROWS   128           // batch rows per CTA
#define NSTEPS 254

// ---- strides (bytes) ----
#define XSB   272            // H activation row stride (136 halfs, 17x16B)
#define XZSB  80             // z-arg row stride (40 halfs, 5x16B)
#define W1SB  80             // W1 row stride
#define WSB   272            // W2/W3 row stride

// ---- smem byte offsets ----
#define OFF_W1    0          // [128][40]  half   10240
#define OFF_W2    10240      // [128][136] half   34816
#define OFF_W3    45056      // [256][136] half   69632
#define OFF_XACT  114688     // H: [128][136] half 34816
#define OFF_XZ    149504     // z-arg: [128][40] half 10240
#define OFF_AC    159744     // f32 [128][33]     16896
#define OFF_DB    176640     // f32 [128][33]     16896
#define OFF_KB    193536     // f32 [128][33]     16896
#define OFF_DX    210432     // f32 [128][8]       4096
#define OFF_RW    214528     // f32 readout        4360
#define SMEM_TOTAL 219136

#define RW1 0
#define RB1 1024
#define RW2 1056
#define RB2 1088

// ---------------- helpers ----------------
static __device__ __forceinline__ uint32_t smem_u32(const void* p) {
    uint32_t a;
    asm("{ .reg .u64 t; cvta.to.shared.u64 t, %1; cvt.u32.u64 %0, t; }" : "=r"(a) : "l"(p));
    return a;
}
static __device__ __forceinline__ float tanh_fast(float x) {
    float y; asm("tanh.approx.f32 %0, %1;" : "=f"(y) : "f"(x)); return y;
}
static __device__ __forceinline__ void ldsm4(uint32_t addr, uint32_t& r0, uint32_t& r1,
                                             uint32_t& r2, uint32_t& r3) {
    asm volatile("ldmatrix.sync.aligned.m8n8.x4.shared.b16 {%0,%1,%2,%3}, [%4];"
        : "=r"(r0), "=r"(r1), "=r"(r2), "=r"(r3) : "r"(addr));
}
static __device__ __forceinline__ void ldsm2(uint32_t addr, uint32_t& r0, uint32_t& r1) {
    asm volatile("ldmatrix.sync.aligned.m8n8.x2.shared.b16 {%0,%1}, [%2];"
        : "=r"(r0), "=r"(r1) : "r"(addr));
}
static __device__ __forceinline__ void mma16(float* c, const uint32_t* a, uint32_t b0, uint32_t b1) {
    asm volatile("mma.sync.aligned.m16n8k16.row.col.f32.f16.f16.f32 "
        "{%0,%1,%2,%3},{%4,%5,%6,%7},{%8,%9},{%0,%1,%2,%3};"
        : "+f"(c[0]), "+f"(c[1]), "+f"(c[2]), "+f"(c[3])
        : "r"(a[0]), "r"(a[1]), "r"(a[2]), "r"(a[3]), "r"(b0), "r"(b1));
}
static __device__ __forceinline__ void mma8(float* c, const uint32_t* a, uint32_t b0) {
    asm volatile("mma.sync.aligned.m16n8k8.row.col.f32.f16.f16.f32 "
        "{%0,%1,%2,%3},{%4,%5},{%6},{%0,%1,%2,%3};"
        : "+f"(c[0]), "+f"(c[1]), "+f"(c[2]), "+f"(c[3])
        : "r"(a[0]), "r"(a[1]), "r"(b0));
}

// ---------------- A-fragment hoist: rows [m0, m0+32), K = 16*KST + 8 ----------------
template<int KST, int XSBI>
static __device__ __forceinline__ void hoistA(
    uint32_t xbase, int m0, int lane, uint32_t AF[][2][4], uint32_t AT[2][2])
{
    const int ar = (lane & 7) + ((lane >> 3) & 1) * 8;
    const int ak = ((lane >> 4) & 1) * 8;
    const int rr = lane & 15;
#pragma unroll
    for (int ks = 0; ks < KST; ks++)
#pragma unroll
        for (int mt = 0; mt < 2; mt++)
            ldsm4(xbase + (uint32_t)(m0 + mt * 16 + ar) * XSBI + (uint32_t)(ks * 16 + ak) * 2,
                  AF[ks][mt][0], AF[ks][mt][1], AF[ks][mt][2], AF[ks][mt][3]);
#pragma unroll
    for (int mt = 0; mt < 2; mt++)
        ldsm2(xbase + (uint32_t)(m0 + mt * 16 + rr) * XSBI + (uint32_t)(KST * 16) * 2,
              AT[mt][0], AT[mt][1]);
}

// ---------------- GEMM compute: M=32 x (NCH x 32 cols starting at nbase) ----------------
// EPI 0: tanh -> H (Xact).  EPI 1: k-epilogue (tanh * dx, c-reduce -> KB).
template<int KST, int NCH, int EPI, int WSBI>
static __device__ __forceinline__ void gemm_compute(
    char* sm, uint32_t wbase, int nbase, int m0, int lane,
    const uint32_t AF[][2][4], const uint32_t AT[2][2])
{
    const int br = (lane & 7) + ((lane >> 4) & 1) * 8;
    const int bk = ((lane >> 3) & 1) * 8;
    const int rr = lane & 15;
    const int g  = lane >> 2;
    const int q2 = (lane & 3) * 2;

#pragma unroll
    for (int ch = 0; ch < NCH; ch++) {
        const int n0 = nbase + ch * 32;
        float acc[2][4][4];
#pragma unroll
        for (int mt = 0; mt < 2; mt++)
#pragma unroll
            for (int nt = 0; nt < 4; nt++)
#pragma unroll
                for (int j = 0; j < 4; j++) acc[mt][nt][j] = 0.0f;

#pragma unroll
        for (int ks = 0; ks < KST; ks++) {
#pragma unroll
            for (int np = 0; np < 2; np++) {
                uint32_t b0, b1, b2, b3;
                ldsm4(wbase + (uint32_t)(n0 + np * 16 + br) * WSBI + (uint32_t)(ks * 16 + bk) * 2,
                      b0, b1, b2, b3);
                mma16(acc[0][2 * np],     AF[ks][0], b0, b1);
                mma16(acc[0][2 * np + 1], AF[ks][0], b2, b3);
                mma16(acc[1][2 * np],     AF[ks][1], b0, b1);
                mma16(acc[1][2 * np + 1], AF[ks][1], b2, b3);
            }
        }
        { // K tail (k8)
#pragma unroll
            for (int np = 0; np < 2; np++) {
                uint32_t b0, b1;
                ldsm2(wbase + (uint32_t)(n0 + np * 16 + rr) * WSBI + (uint32_t)(KST * 16) * 2,
                      b0, b1);
                mma8(acc[0][2 * np],     AT[0], b0);
                mma8(acc[0][2 * np + 1], AT[0], b1);
                mma8(acc[1][2 * np],     AT[1], b0);
                mma8(acc[1][2 * np + 1], AT[1], b1);
            }
        }

        if (EPI == 0) {
#pragma unroll
            for (int mt = 0; mt < 2; mt++) {
                int rowA = m0 + mt * 16 + g;
#pragma unroll
                for (int nt = 0; nt < 4; nt++) {
                    int col = n0 + nt * 8 + q2;
                    __half2 lo = __floats2half2_rn(tanh_fast(acc[mt][nt][0]), tanh_fast(acc[mt][nt][1]));
                    __half2 hi = __floats2half2_rn(tanh_fast(acc[mt][nt][2]), tanh_fast(acc[mt][nt][3]));
                    *(__half2*)(sm + OFF_XACT + (size_t)rowA * XSB + col * 2)       = lo;
                    *(__half2*)(sm + OFF_XACT + (size_t)(rowA + 8) * XSB + col * 2) = hi;
                }
            }
        } else {
            const float* dxs = (const float*)(sm + OFF_DX);
            float* kb = (float*)(sm + OFF_KB);
#pragma unroll
            for (int mt = 0; mt < 2; mt++) {
                int rA = m0 + mt * 16 + g, rB = rA + 8;
                float2 dA = *(const float2*)(dxs + rA * 8 + q2);
                float2 dB = *(const float2*)(dxs + rB * 8 + q2);
#pragma unroll
                for (int nt = 0; nt < 4; nt++) {
                    int h = (n0 >> 3) + nt;
                    float pA = tanh_fast(acc[mt][nt][0]) * dA.x + tanh_fast(acc[mt][nt][1]) * dA.y;
                    float pB = tanh_fast(acc[mt][nt][2]) * dB.x + tanh_fast(acc[mt][nt][3]) * dB.y;
                    pA += __shfl_xor_sync(0xFFFFFFFFu, pA, 1);
                    pA += __shfl_xor_sync(0xFFFFFFFFu, pA, 2);
                    pB += __shfl_xor_sync(0xFFFFFFFFu, pB, 1);
                    pB += __shfl_xor_sync(0xFFFFFFFFu, pB, 2);
                    if ((lane & 3) == 0) {
                        kb[rA * 33 + h] = pA;
                        kb[rB * 33 + h] = pB;
                    }
                }
            }
        }
    }
}

// ---------------- kernel ----------------
__global__ void __launch_bounds__(TPB, 1) cde_kernel(
    const float* __restrict__ coeffs,
    const float* __restrict__ iW1, const float* __restrict__ ib1,
    const float* __restrict__ iW2, const float* __restrict__ ib2,
    const float* __restrict__ fW1, const float* __restrict__ fb1,
    const float* __restrict__ fW2, const float* __restrict__ fb2,
    const float* __restrict__ fW3, const float* __restrict__ fb3,
    const float* __restrict__ rW1, const float* __restrict__ rb1,
    const float* __restrict__ rW2, const float* __restrict__ rb2,
    float* __restrict__ out)
{
    extern __shared__ char sm[];
    const uint32_t smb = smem_u32(sm);
    const int tid  = threadIdx.x;
    const int lane = tid & 31;
    const int wid  = tid >> 5;
    const int m0   = (wid & 3) * 32;                     // M-group: 32 rows
    const int ng   = wid >> 2;                           // N-group: 0 or 1
    const bool owner = tid < ROWS;
    const size_t b = (size_t)blockIdx.x * ROWS + tid;    // valid only when owner

    // ========== weight staging: fp16 [N][K] row-major, bias folded at k=K_real ==========
    for (int e = tid; e < 128 * 40; e += TPB) {
        int n = e / 40, k = e % 40;
        float v = (k < 32) ? fW1[k * 128 + n] : (k == 32 ? fb1[n] : 0.0f);
        *(__half*)(sm + OFF_W1 + (size_t)n * W1SB + k * 2) = __float2half_rn(v);
    }
    for (int e = tid; e < 128 * 136; e += TPB) {
        int n = e / 136, k = e % 136;
        float v = (k < 128) ? fW2[k * 128 + n] : (k == 128 ? fb2[n] : 0.0f);
        *(__half*)(sm + OFF_W2 + (size_t)n * WSB + k * 2) = __float2half_rn(v);
    }
    for (int e = tid; e < 256 * 136; e += TPB) {
        int n = e / 136, k = e % 136;
        float v = (k < 128) ? fW3[k * 256 + n] : (k == 128 ? fb3[n] : 0.0f);
        *(__half*)(sm + OFF_W3 + (size_t)n * WSB + k * 2) = __float2half_rn(v);
    }
    {
        float* rw = (float*)(sm + OFF_RW);
        for (int i = tid; i < 1024; i += TPB) rw[RW1 + i] = rW1[i];
        if (tid < 32) { rw[RB1 + tid] = rb1[tid]; rw[RW2 + tid] = rW2[tid]; }
        if (tid == 0) rw[RB2] = rb2[0];
    }
    // H buffer bias cols (128..135): bias=1 at 128, zeros after (rows staged by all threads)
    for (int r = tid; r < ROWS; r += TPB) {
        __half2* hr = (__half2*)(sm + OFF_XACT + (size_t)r * XSB);
        hr[64] = __floats2half2_rn(1.0f, 0.0f);
        hr[65] = hr[66] = hr[67] = __floats2half2_rn(0.0f, 0.0f);
    }

    // ========== z0 = initial(X(0)) (owners only) ==========
    const float* base_c = coeffs + (owner ? b : 0) * (size_t)(127 * 32);
    float z[32];
    __half2* xz = (__half2*)(sm + OFF_XZ + (size_t)(owner ? tid : 0) * XZSB);
    if (owner) {
        float X0[8];
        float4 q0 = *(const float4*)(base_c + 0);
        float4 q1 = *(const float4*)(base_c + 4);
        X0[0]=q0.x; X0[1]=q0.y; X0[2]=q0.z; X0[3]=q0.w;
        X0[4]=q1.x; X0[5]=q1.y; X0[6]=q1.z; X0[7]=q1.w;
#pragma unroll
        for (int i = 0; i < 32; i++) z[i] = ib2[i];
        for (int j = 0; j < 64; j++) {
            float hj = ib1[j];
#pragma unroll
            for (int c = 0; c < 8; c++) hj += X0[c] * iW1[c * 64 + j];
            hj = fmaxf(hj, 0.0f);
#pragma unroll
            for (int i = 0; i < 32; i++) z[i] += hj * iW2[j * 32 + i];
        }
        // initial z-arg + static bias cols (combine only ever rewrites cols 0..31)
#pragma unroll
        for (int i = 0; i < 16; i++) xz[i] = __floats2half2_rn(z[2 * i], z[2 * i + 1]);
        xz[16] = __floats2half2_rn(1.0f, 0.0f);
        xz[17] = xz[18] = xz[19] = __floats2half2_rn(0.0f, 0.0f);
    }
    __syncthreads();

    // ---- knot 0 readout ----
    if (owner) {
        const float* rw = (const float*)(sm + OFF_RW);
        float h[32];
#pragma unroll
        for (int j = 0; j < 32; j++) h[j] = rw[RB1 + j];
#pragma unroll
        for (int i = 0; i < 32; i++) {
            float zi = z[i];
#pragma unroll
            for (int j = 0; j < 32; j++) h[j] += zi * rw[RW1 + i * 32 + j];
        }
        float y = rw[RB2];
#pragma unroll
        for (int j = 0; j < 32; j++) y += fmaxf(h[j], 0.0f) * rw[RW2 + j];
        out[b * 128] = y;
    }

    // ========== RK4 (3/8 rule) main loop ==========
    float* acp = (float*)(sm + OFF_AC) + tid * 33;
    float* dbp = (float*)(sm + OFF_DB) + tid * 33;
    float* kbp = (float*)(sm + OFF_KB) + tid * 33;
    float* dxp = (float*)(sm + OFF_DX) + tid * 8;

    int cur = -1;
    float cb[8], c2r[8], c3r[8];

    uint32_t AF[8][2][4], AT[2][2];

#pragma unroll 1
    for (int step = 0; step < NSTEPS; step++) {
        const float t0 = 0.5f * (float)step;
#pragma unroll 1
        for (int s = 0; s < 4; s++) {
            // ---- dx(ts) for own row -> smem (owners) ----
            if (owner) {
                float ts = t0 + (s == 0 ? 0.0f : s == 1 ? 0.16666667f
                                               : s == 2 ? 0.33333334f : 0.5f);
                int id = (int)ts; if (id > 126) id = 126;
                float fr = ts - (float)id;
                if (id != cur) {
                    cur = id;
                    const float4* cp = (const float4*)(base_c + (size_t)id * 32);
                    float4 q;
                    q = cp[2]; cb[0]=q.x;  cb[1]=q.y;  cb[2]=q.z;  cb[3]=q.w;
                    q = cp[3]; cb[4]=q.x;  cb[5]=q.y;  cb[6]=q.z;  cb[7]=q.w;
                    q = cp[4]; c2r[0]=q.x; c2r[1]=q.y; c2r[2]=q.z; c2r[3]=q.w;
                    q = cp[5]; c2r[4]=q.x; c2r[5]=q.y; c2r[6]=q.z; c2r[7]=q.w;
                    q = cp[6]; c3r[0]=q.x; c3r[1]=q.y; c3r[2]=q.z; c3r[3]=q.w;
                    q = cp[7]; c3r[4]=q.x; c3r[5]=q.y; c3r[6]=q.z; c3r[7]=q.w;
                }
#pragma unroll
                for (int c = 0; c < 8; c++)
                    dxp[c] = cb[c] + (c2r[c] + c3r[c] * fr) * fr;
            }
            __syncthreads();   // barA: z-arg (Xz) + DX published

            // ---- layer 1: Xz (K=40) -> H cols [64ng, 64ng+64) ----
            hoistA<2, XZSB>(smb + OFF_XZ, m0, lane, AF, AT);
            gemm_compute<2, 2, 0, W1SB>(sm, smb + OFF_W1, ng * 64, m0, lane, AF, AT);
            __syncthreads();   // b1: h1 published

            // ---- layer 2: H (K=136) -> H in place (hoist/write split) ----
            hoistA<8, XSB>(smb + OFF_XACT, m0, lane, AF, AT);
            __syncthreads();   // b2: all hoists done before in-place writes
            gemm_compute<8, 2, 0, WSB>(sm, smb + OFF_W2, ng * 64, m0, lane, AF, AT);
            __syncthreads();   // b3: h2 published

            // ---- layer 3: H (K=136) -> k-epilogue -> KB ----
            hoistA<8, XSB>(smb + OFF_XACT, m0, lane, AF, AT);
            gemm_compute<8, 4, 1, WSB>(sm, smb + OFF_W3, ng * 128, m0, lane, AF, AT);
            __syncthreads();   // barB: KB published

            // ---- RK4 combination (owner thread = own row), write next arg ----
            if (owner) {
#pragma unroll
                for (int i = 0; i < 32; i += 2) {
                    float k0 = kbp[i], k1 = kbp[i + 1];
                    float v0, v1;
                    if (s == 0) {
                        acp[i] = k0; acp[i + 1] = k1;
                        dbp[i] = k0; dbp[i + 1] = k1;
                        v0 = z[i]     + k0 * (1.0f / 6.0f);
                        v1 = z[i + 1] + k1 * (1.0f / 6.0f);
                    } else if (s == 1) {
                        float a0 = acp[i] + 3.0f * k0, a1 = acp[i + 1] + 3.0f * k1;
                        float d0 = dbp[i] - k0,        d1 = dbp[i + 1] - k1;
                        acp[i] = a0; acp[i + 1] = a1;
                        dbp[i] = d0; dbp[i + 1] = d1;
                        v0 = z[i]     + (a0 - 3.0f * d0) * (1.0f / 12.0f);
                        v1 = z[i + 1] + (a1 - 3.0f * d1) * (1.0f / 12.0f);
                    } else if (s == 2) {
                        float a0 = acp[i] + 3.0f * k0, a1 = acp[i + 1] + 3.0f * k1;
                        float d0 = dbp[i] + k0,        d1 = dbp[i + 1] + k1;
                        acp[i] = a0; acp[i + 1] = a1;
                        dbp[i] = d0; dbp[i + 1] = d1;
                        v0 = z[i]     + 0.5f * d0;
                        v1 = z[i + 1] + 0.5f * d1;
                    } else {
                        z[i]     += 0.0625f * (acp[i]     + k0);
                        z[i + 1] += 0.0625f * (acp[i + 1] + k1);
                        v0 = z[i]; v1 = z[i + 1];
                    }
                    xz[i >> 1] = __floats2half2_rn(v0, v1);
                }
            }
            // barA of next sub-step publishes xz before the next layer-1
        }

        // ---- readout at integer knots ----
        if ((step & 1) && owner) {
            const float* rw = (const float*)(sm + OFF_RW);
            float h[32];
#pragma unroll
            for (int j = 0; j < 32; j++) h[j] = rw[RB1 + j];
#pragma unroll
            for (int i = 0; i < 32; i++) {
                float zi = z[i];
#pragma unroll
                for (int j = 0; j < 32; j++) h[j] += zi * rw[RW1 + i * 32 + j];
            }
            float y = rw[RB2];
#pragma unroll
            for (int j = 0; j < 32; j++) y += fmaxf(h[j], 0.0f) * rw[RW2 + j];
            out[b * 128 + (size_t)((step >> 1) + 1)] = y;
        }
    }
}

extern "C" void kernel_launch(void* const* d_in, const int* in_sizes, int n_in,
                              void* d_out, int out_size)
{
    (void)in_sizes; (void)n_in; (void)out_size;
    cudaFuncSetAttribute(cde_kernel, cudaFuncAttributeMaxDynamicSharedMemorySize, SMEM_TOTAL);
    cde_kernel<<<128, TPB, SMEM_TOTAL>>>(
        (const float*)d_in[0],                              // coeffs (d_in[1]=t_eval unused)
        (const float*)d_in[2],  (const float*)d_in[3],      // iW1, ib1
        (const float*)d_in[4],  (const float*)d_in[5],      // iW2, ib2
        (const float*)d_in[6],  (const float*)d_in[7],      // fW1, fb1
        (const float*)d_in[8],  (const float*)d_in[9],      // fW2, fb2
        (const float*)d_in[10], (const float*)d_in[11],     // fW3, fb3
        (const float*)d_in[12], (const float*)d_in[13],     // rW1, rb1
        (const float*)d_in[14], (const float*)d_in[15],     // rW2, rb2
        (float*)d_out);
}

// round 17
// speedup vs baseline: 1.0842x; 1.0842x over previous
#include <cuda_runtime.h>
#include <cuda_fp16.h>
#include <cstdint>

#define TPB    512           // 16 warps = 8 pairs; pair p owns rows 16p..16p+15
#define ROWS   128
#define NSTEPS 254

// ---- strides (bytes) ----
#define XSB   272            // H row stride (17x16B, conflict-free ldmatrix; cols 0..127 used)
#define XZSB  80             // z-arg row stride (5x16B; cols 0..31 used)
#define W1SB  80             // W1 row stride (k 0..31 used)
#define WSB   272            // W2/W3 row stride (k 0..127 used)

// ---- smem byte offsets ----
#define OFF_W1    0          // [128][80B]        10240
#define OFF_W2    10240      // [128][272B]       34816
#define OFF_W3    45056      // [256][272B]       69632
#define OFF_H1    114688     // L1 out / L2 in    34816
#define OFF_H2    149504     // L2 out / L3 in    34816
#define OFF_XZ    184320     // z-arg [128][80B]  10240
#define OFF_KB    194560     // f32 [128][33]     16896
#define OFF_DX    211456     // f32 [128][8]       4096
#define OFF_RW    215552     // f32 readout        4360
#define OFF_BS    219920     // f32 biases         2048
#define SMEM_TOTAL 221968

#define RW1 0
#define RB1 1024
#define RW2 1056
#define RB2 1088

// ---------------- helpers ----------------
static __device__ __forceinline__ uint32_t smem_u32(const void* p) {
    uint32_t a;
    asm("{ .reg .u64 t; cvta.to.shared.u64 t, %1; cvt.u32.u64 %0, t; }" : "=r"(a) : "l"(p));
    return a;
}
static __device__ __forceinline__ float tanh_fast(float x) {
    float y; asm("tanh.approx.f32 %0, %1;" : "=f"(y) : "f"(x)); return y;
}
static __device__ __forceinline__ void ldsm4(uint32_t addr, uint32_t& r0, uint32_t& r1,
                                             uint32_t& r2, uint32_t& r3) {
    asm volatile("ldmatrix.sync.aligned.m8n8.x4.shared.b16 {%0,%1,%2,%3}, [%4];"
        : "=r"(r0), "=r"(r1), "=r"(r2), "=r"(r3) : "r"(addr));
}
static __device__ __forceinline__ void mma16(float* c, const uint32_t* a, uint32_t b0, uint32_t b1) {
    asm volatile("mma.sync.aligned.m16n8k16.row.col.f32.f16.f16.f32 "
        "{%0,%1,%2,%3},{%4,%5,%6,%7},{%8,%9},{%0,%1,%2,%3};"
        : "+f"(c[0]), "+f"(c[1]), "+f"(c[2]), "+f"(c[3])
        : "r"(a[0]), "r"(a[1]), "r"(a[2]), "r"(a[3]), "r"(b0), "r"(b1));
}
#define PAIR_BAR(id) asm volatile("bar.sync %0, 64;" :: "r"(id) : "memory")

// ---------------- A-fragment hoist: rows [m0, m0+16), K = 16*KST ----------------
template<int KST, int XSBI>
static __device__ __forceinline__ void hoistA(
    uint32_t xbase, int m0, int lane, uint32_t AF[][4])
{
    const int ar = (lane & 7) + ((lane >> 3) & 1) * 8;
    const int ak = ((lane >> 4) & 1) * 8;
#pragma unroll
    for (int ks = 0; ks < KST; ks++)
        ldsm4(xbase + (uint32_t)(m0 + ar) * XSBI + (uint32_t)(ks * 16 + ak) * 2,
              AF[ks][0], AF[ks][1], AF[ks][2], AF[ks][3]);
}

// ---------------- GEMM compute: M=16, NCH chunks of 32 cols at nbase ----------------
// EPI 0: tanh -> H at houto.  EPI 1: k-epilogue (tanh * dx, c-reduce -> KB).
template<int KST, int NCH, int EPI, int WSBI>
static __device__ __forceinline__ void gemm_compute(
    char* sm, uint32_t wbase, const float* bias, int nbase, int m0, int lane,
    const uint32_t AF[][4], int houto)
{
    const int br = (lane & 7) + ((lane >> 4) & 1) * 8;
    const int bk = ((lane >> 3) & 1) * 8;
    const int g  = lane >> 2;
    const int q2 = (lane & 3) * 2;

#pragma unroll
    for (int ch = 0; ch < NCH; ch++) {
        const int n0 = nbase + ch * 32;
        float acc[4][4];
#pragma unroll
        for (int nt = 0; nt < 4; nt++) {
            float2 bv = *(const float2*)(bias + n0 + nt * 8 + q2);
            acc[nt][0] = bv.x; acc[nt][1] = bv.y;
            acc[nt][2] = bv.x; acc[nt][3] = bv.y;
        }
#pragma unroll
        for (int ks = 0; ks < KST; ks++) {
#pragma unroll
            for (int np = 0; np < 2; np++) {
                uint32_t b0, b1, b2, b3;
                ldsm4(wbase + (uint32_t)(n0 + np * 16 + br) * WSBI + (uint32_t)(ks * 16 + bk) * 2,
                      b0, b1, b2, b3);
                mma16(acc[2 * np],     AF[ks], b0, b1);
                mma16(acc[2 * np + 1], AF[ks], b2, b3);
            }
        }

        if (EPI == 0) {
            int rowA = m0 + g;
#pragma unroll
            for (int nt = 0; nt < 4; nt++) {
                int col = n0 + nt * 8 + q2;
                __half2 lo = __floats2half2_rn(tanh_fast(acc[nt][0]), tanh_fast(acc[nt][1]));
                __half2 hi = __floats2half2_rn(tanh_fast(acc[nt][2]), tanh_fast(acc[nt][3]));
                *(__half2*)(sm + houto + (size_t)rowA * XSB + col * 2)       = lo;
                *(__half2*)(sm + houto + (size_t)(rowA + 8) * XSB + col * 2) = hi;
            }
        } else {
            const float* dxs = (const float*)(sm + OFF_DX);
            float* kb = (float*)(sm + OFF_KB);
            int rA = m0 + g, rB = rA + 8;
            float2 dA = *(const float2*)(dxs + rA * 8 + q2);
            float2 dB = *(const float2*)(dxs + rB * 8 + q2);
#pragma unroll
            for (int nt = 0; nt < 4; nt++) {
                int h = (n0 >> 3) + nt;
                float pA = tanh_fast(acc[nt][0]) * dA.x + tanh_fast(acc[nt][1]) * dA.y;
                float pB = tanh_fast(acc[nt][2]) * dB.x + tanh_fast(acc[nt][3]) * dB.y;
                pA += __shfl_xor_sync(0xFFFFFFFFu, pA, 1);
                pA += __shfl_xor_sync(0xFFFFFFFFu, pA, 2);
                pB += __shfl_xor_sync(0xFFFFFFFFu, pB, 1);
                pB += __shfl_xor_sync(0xFFFFFFFFu, pB, 2);
                if ((lane & 3) == 0) {
                    kb[rA * 33 + h] = pA;
                    kb[rB * 33 + h] = pB;
                }
            }
        }
    }
}

// ---------------- kernel ----------------
__global__ void __launch_bounds__(TPB, 1) cde_kernel(
    const float* __restrict__ coeffs,
    const float* __restrict__ iW1, const float* __restrict__ ib1,
    const float* __restrict__ iW2, const float* __restrict__ ib2,
    const float* __restrict__ fW1, const float* __restrict__ fb1,
    const float* __restrict__ fW2, const float* __restrict__ fb2,
    const float* __restrict__ fW3, const float* __restrict__ fb3,
    const float* __restrict__ rW1, const float* __restrict__ rb1,
    const float* __restrict__ rW2, const float* __restrict__ rb2,
    float* __restrict__ out)
{
    extern __shared__ char sm[];
    const uint32_t smb = smem_u32(sm);
    const int tid  = threadIdx.x;
    const int lane = tid & 31;
    const int wid  = tid >> 5;
    const int pair = wid >> 1;
    const int half = wid & 1;
    const int m0   = pair * 16;
    // combine/readout assignment: 4 threads per row, 8 z-components each
    const int r    = tid >> 2;
    const int q    = tid & 3;
    const int j0   = q * 8;
    const int c0   = q * 2;           // dx channel slice
    const size_t brow = (size_t)blockIdx.x * ROWS + r;

    // ========== weight staging ==========
    for (int e = tid; e < 128 * 32; e += TPB) {
        int n = e >> 5, k = e & 31;
        *(__half*)(sm + OFF_W1 + (size_t)n * W1SB + k * 2) = __float2half_rn(fW1[k * 128 + n]);
    }
    for (int e = tid; e < 128 * 128; e += TPB) {
        int n = e >> 7, k = e & 127;
        *(__half*)(sm + OFF_W2 + (size_t)n * WSB + k * 2) = __float2half_rn(fW2[k * 128 + n]);
    }
    for (int e = tid; e < 256 * 128; e += TPB) {
        int n = e >> 7, k = e & 127;
        *(__half*)(sm + OFF_W3 + (size_t)n * WSB + k * 2) = __float2half_rn(fW3[k * 256 + n]);
    }
    {
        float* rw = (float*)(sm + OFF_RW);
        for (int i = tid; i < 1024; i += TPB) rw[RW1 + i] = rW1[i];
        if (tid < 32) { rw[RB1 + tid] = rb1[tid]; rw[RW2 + tid] = rW2[tid]; }
        if (tid == 0) rw[RB2] = rb2[0];
        float* bs = (float*)(sm + OFF_BS);
        if (tid < 128) { bs[tid] = fb1[tid]; bs[128 + tid] = fb2[tid]; }
        if (tid < 256) bs[256 + tid] = fb3[tid];
    }

    // ========== z0 = initial(X(0)): each thread computes its 8 components ==========
    const float* base_c = coeffs + brow * (size_t)(127 * 32);
    float zr[8], ac[8], db[8];
    {
        float X0[8];
        float4 q0 = *(const float4*)(base_c + 0);
        float4 q1 = *(const float4*)(base_c + 4);
        X0[0]=q0.x; X0[1]=q0.y; X0[2]=q0.z; X0[3]=q0.w;
        X0[4]=q1.x; X0[5]=q1.y; X0[6]=q1.z; X0[7]=q1.w;
#pragma unroll
        for (int jj = 0; jj < 8; jj++) zr[jj] = ib2[j0 + jj];
        for (int k = 0; k < 64; k++) {
            float hk = ib1[k];
#pragma unroll
            for (int c = 0; c < 8; c++) hk += X0[c] * iW1[c * 64 + k];
            hk = fmaxf(hk, 0.0f);
#pragma unroll
            for (int jj = 0; jj < 8; jj++) zr[jj] += hk * iW2[k * 32 + j0 + jj];
        }
        __half2* xzr = (__half2*)(sm + OFF_XZ + (size_t)r * XZSB);
#pragma unroll
        for (int p = 0; p < 4; p++)
            xzr[q * 4 + p] = __floats2half2_rn(zr[2 * p], zr[2 * p + 1]);
    }
    __syncthreads();

    // ---- distributed readout (knot emit): 4 threads/row, shfl-reduced ----
    const float* rws = (const float*)(sm + OFF_RW);
#define EMIT_KNOT(knot) do { \
        float hp[32]; \
        _Pragma("unroll") \
        for (int j = 0; j < 32; j++) hp[j] = (q == 0) ? rws[RB1 + j] : 0.0f; \
        _Pragma("unroll") \
        for (int jj = 0; jj < 8; jj++) { \
            float zi = zr[jj]; \
            const float* wrow = rws + RW1 + (j0 + jj) * 32; \
            _Pragma("unroll") \
            for (int j = 0; j < 32; j++) hp[j] += zi * wrow[j]; \
        } \
        _Pragma("unroll") \
        for (int j = 0; j < 32; j++) { \
            hp[j] += __shfl_xor_sync(0xFFFFFFFFu, hp[j], 1); \
            hp[j] += __shfl_xor_sync(0xFFFFFFFFu, hp[j], 2); \
        } \
        float y = 0.0f; \
        _Pragma("unroll") \
        for (int jj = 0; jj < 8; jj++) y += fmaxf(hp[j0 + jj], 0.0f) * rws[RW2 + j0 + jj]; \
        y += __shfl_xor_sync(0xFFFFFFFFu, y, 1); \
        y += __shfl_xor_sync(0xFFFFFFFFu, y, 2); \
        if (q == 0) out[brow * 128 + (size_t)(knot)] = y + rws[RB2]; \
    } while (0)

    EMIT_KNOT(0);

    // ========== RK4 (3/8 rule) main loop ==========
    const float* bsf = (const float*)(sm + OFF_BS);
    float* dxp = (float*)(sm + OFF_DX) + r * 8 + c0;
    const float* kbrow = (const float*)(sm + OFF_KB) + r * 33 + j0;
    __half2* xzr = (__half2*)(sm + OFF_XZ + (size_t)r * XZSB) + q * 4;

    int cur = -1;
    float cbx0, cbx1, c2x0, c2x1, c3x0, c3x1;
    uint32_t AF[8][4];

#pragma unroll 1
    for (int step = 0; step < NSTEPS; step++) {
        const float t0 = 0.5f * (float)step;
#pragma unroll 1
        for (int s = 0; s < 4; s++) {
            // ---- dx(ts): each thread computes 2 channels for its row ----
            {
                float ts = t0 + (s == 0 ? 0.0f : s == 1 ? 0.16666667f
                                               : s == 2 ? 0.33333334f : 0.5f);
                int id = (int)ts; if (id > 126) id = 126;
                float fr = ts - (float)id;
                if (id != cur) {               // warp-uniform branch (ts is global)
                    cur = id;
                    const float* cf = base_c + (size_t)id * 32;
                    float2 bb = *(const float2*)(cf + 8 + c0);
                    float2 b2 = *(const float2*)(cf + 16 + c0);
                    float2 b3 = *(const float2*)(cf + 24 + c0);
                    cbx0 = bb.x; cbx1 = bb.y;
                    c2x0 = b2.x; c2x1 = b2.y;
                    c3x0 = b3.x; c3x1 = b3.y;
                }
                float2 dv;
                dv.x = cbx0 + (c2x0 + c3x0 * fr) * fr;
                dv.y = cbx1 + (c2x1 + c3x1 * fr) * fr;
                *(float2*)dxp = dv;
            }
            __syncthreads();   // barA: Xz + DX published

            // ---- layer 1: Xz (K=32) -> H1 cols [64h, 64h+64) ----
            hoistA<2, XZSB>(smb + OFF_XZ, m0, lane, AF);
            gemm_compute<2, 2, 0, W1SB>(sm, smb + OFF_W1, bsf, 64 * half, m0, lane, AF, OFF_H1);
            PAIR_BAR(1 + pair);

            // ---- layer 2: H1 (K=128) -> H2 cols [64h, 64h+64) ----
            hoistA<8, XSB>(smb + OFF_H1, m0, lane, AF);
            gemm_compute<8, 2, 0, WSB>(sm, smb + OFF_W2, bsf + 128, 64 * half, m0, lane, AF, OFF_H2);
            PAIR_BAR(1 + pair);

            // ---- layer 3: H2 (K=128) -> k-epilogue -> KB ----
            hoistA<8, XSB>(smb + OFF_H2, m0, lane, AF);
            gemm_compute<8, 4, 1, WSB>(sm, smb + OFF_W3, bsf + 256, 128 * half, m0, lane, AF, 0);
            __syncthreads();   // barB: KB published

            // ---- RK4 combination: each thread updates its 8 components ----
            {
                float kk[8];
#pragma unroll
                for (int jj = 0; jj < 8; jj++) kk[jj] = kbrow[jj];
                float v[8];
                if (s == 0) {
#pragma unroll
                    for (int jj = 0; jj < 8; jj++) {
                        ac[jj] = kk[jj]; db[jj] = kk[jj];
                        v[jj] = zr[jj] + kk[jj] * (1.0f / 6.0f);
                    }
                } else if (s == 1) {
#pragma unroll
                    for (int jj = 0; jj < 8; jj++) {
                        ac[jj] += 3.0f * kk[jj]; db[jj] -= kk[jj];
                        v[jj] = zr[jj] + (ac[jj] - 3.0f * db[jj]) * (1.0f / 12.0f);
                    }
                } else if (s == 2) {
#pragma unroll
                    for (int jj = 0; jj < 8; jj++) {
                        ac[jj] += 3.0f * kk[jj]; db[jj] += kk[jj];
                        v[jj] = zr[jj] + 0.5f * db[jj];
                    }
                } else {
#pragma unroll
                    for (int jj = 0; jj < 8; jj++) {
                        zr[jj] += 0.0625f * (ac[jj] + kk[jj]);
                        v[jj] = zr[jj];
                    }
                }
#pragma unroll
                for (int p = 0; p < 4; p++)
                    xzr[p] = __floats2half2_rn(v[2 * p], v[2 * p + 1]);
            }
            // barA of next sub-step publishes xz before the next layer-1
        }

        if (step & 1) EMIT_KNOT((step >> 1) + 1);
    }
}

extern "C" void kernel_launch(void* const* d_in, const int* in_sizes, int n_in,
                              void* d_out, int out_size)
{
    (void)in_sizes; (void)n_in; (void)out_size;
    cudaFuncSetAttribute(cde_kernel, cudaFuncAttributeMaxDynamicSharedMemorySize, SMEM_TOTAL);
    cde_kernel<<<128, TPB, SMEM_TOTAL>>>(
        (const float*)d_in[0],                              // coeffs (d_in[1]=t_eval unused)
        (const float*)d_in[2],  (const float*)d_in[3],      // iW1, ib1
        (const float*)d_in[4],  (const float*)d_in[5],      // iW2, ib2
        (const float*)d_in[6],  (const float*)d_in[7],      // fW1, fb1
        (const float*)d_in[8],  (const float*)d_in[9],      // fW2, fb2
        (const float*)d_in[10], (const float*)d_in[11],     // fW3, fb3
        (const float*)d_in[12], (const float*)d_in[13],     // rW1, rb1
        (const float*)d_in[14], (const float*)d_in[15],     // rW2, rb2
        (float*)d_out);
}